// round 1
// baseline (speedup 1.0000x reference)
#include <cuda_runtime.h>
#include <math.h>

#define TT 2048
#define HIDD 2048
#define NH 32
#define DH 64
#define KD 2048
#define NE (2048u*2048u)

// Scratch: q,k,v,g projections; qc,kc,vc post-conv; o scan output; alpha/beta.
__device__ __align__(16) float g_scratch[8ull*NE + 2ull*TT*NH];

#define OFF_Q  (0ull*NE)
#define OFF_K  (1ull*NE)
#define OFF_V  (2ull*NE)
#define OFF_G  (3ull*NE)
#define OFF_QC (4ull*NE)
#define OFF_KC (5ull*NE)
#define OFF_VC (6ull*NE)
#define OFF_O  (7ull*NE)
#define OFF_AL (8ull*NE)
#define OFF_BE (8ull*NE + (unsigned long long)TT*NH)

// ---------------------------------------------------------------------------
// NT SGEMM: C[m,n] = sum_k A[m*K+k] * B[n*K+k].  128x128 tile, BK=8, 8x8/thread.
// ---------------------------------------------------------------------------
__global__ __launch_bounds__(256) void sgemm_nt(const float* __restrict__ A,
                                                const float* __restrict__ B,
                                                float* __restrict__ C,
                                                int M, int N, int K) {
    __shared__ __align__(16) float As[8][128];
    __shared__ __align__(16) float Bs[8][128];
    const int tid = threadIdx.x;
    const int lr = tid >> 1;           // row within 128-tile for loading
    const int lc = (tid & 1) << 2;     // k offset 0 or 4
    const int tx = tid & 15;           // n micro
    const int ty = tid >> 4;           // m micro

    const float* Ap = A + (size_t)(blockIdx.y * 128 + lr) * K + lc;
    const float* Bp = B + (size_t)(blockIdx.x * 128 + lr) * K + lc;

    float acc[8][8];
#pragma unroll
    for (int i = 0; i < 8; i++)
#pragma unroll
        for (int j = 0; j < 8; j++) acc[i][j] = 0.f;

    for (int k0 = 0; k0 < K; k0 += 8) {
        float4 a4 = *(const float4*)(Ap + k0);
        float4 b4 = *(const float4*)(Bp + k0);
        As[lc + 0][lr] = a4.x; As[lc + 1][lr] = a4.y;
        As[lc + 2][lr] = a4.z; As[lc + 3][lr] = a4.w;
        Bs[lc + 0][lr] = b4.x; Bs[lc + 1][lr] = b4.y;
        Bs[lc + 2][lr] = b4.z; Bs[lc + 3][lr] = b4.w;
        __syncthreads();
#pragma unroll
        for (int kk = 0; kk < 8; kk++) {
            float ar[8], br[8];
            *(float4*)&ar[0] = *(const float4*)&As[kk][ty * 8];
            *(float4*)&ar[4] = *(const float4*)&As[kk][ty * 8 + 4];
            *(float4*)&br[0] = *(const float4*)&Bs[kk][tx * 8];
            *(float4*)&br[4] = *(const float4*)&Bs[kk][tx * 8 + 4];
#pragma unroll
            for (int i = 0; i < 8; i++)
#pragma unroll
                for (int j = 0; j < 8; j++)
                    acc[i][j] += ar[i] * br[j];
        }
        __syncthreads();
    }
    float* Cp = C + (size_t)(blockIdx.y * 128 + ty * 8) * N + blockIdx.x * 128 + tx * 8;
#pragma unroll
    for (int i = 0; i < 8; i++) {
        *(float4*)(Cp + (size_t)i * N)     = make_float4(acc[i][0], acc[i][1], acc[i][2], acc[i][3]);
        *(float4*)(Cp + (size_t)i * N + 4) = make_float4(acc[i][4], acc[i][5], acc[i][6], acc[i][7]);
    }
}

// ---------------------------------------------------------------------------
// Causal depthwise conv (K=4) + SiLU.  One thread per (t, c).
// ---------------------------------------------------------------------------
__global__ __launch_bounds__(256) void conv_silu(const float* __restrict__ in,
                                                 const float* __restrict__ w,
                                                 const float* __restrict__ b,
                                                 float* __restrict__ out) {
    unsigned idx = blockIdx.x * 256u + threadIdx.x;   // t*KD + c
    int c = idx & (KD - 1);
    int t = idx >> 11;
    float4 w4 = ((const float4*)w)[c];
    float y = b[c];
    int ts = t - 3;
    if (ts >= 0)     y += in[(size_t)ts * KD + c] * w4.x;
    if (ts + 1 >= 0) y += in[(size_t)(ts + 1) * KD + c] * w4.y;
    if (ts + 2 >= 0) y += in[(size_t)(ts + 2) * KD + c] * w4.z;
    y += in[(size_t)t * KD + c] * w4.w;
    out[idx] = y / (1.f + expf(-y));   // silu
}

// ---------------------------------------------------------------------------
// beta / alpha: beta = sigmoid(x@Wb.T + bb);
// alpha = exp(-exp(A_log) * softplus(x@Wgk.T + bgk + dt_bias))
// One block per t; 8 warps, 4 heads per warp.
// ---------------------------------------------------------------------------
__global__ __launch_bounds__(256) void small_proj(const float* __restrict__ x,
                                                  const float* __restrict__ Wb,
                                                  const float* __restrict__ bb,
                                                  const float* __restrict__ Wgk,
                                                  const float* __restrict__ bgk,
                                                  const float* __restrict__ A_log,
                                                  const float* __restrict__ dt_bias,
                                                  float* __restrict__ alpha,
                                                  float* __restrict__ beta) {
    __shared__ __align__(16) float xs[HIDD];
    int t = blockIdx.x;
    for (int i = threadIdx.x; i < HIDD / 4; i += 256)
        ((float4*)xs)[i] = ((const float4*)(x + (size_t)t * HIDD))[i];
    __syncthreads();
    int warp = threadIdx.x >> 5, lane = threadIdx.x & 31;
#pragma unroll
    for (int hh = 0; hh < 4; hh++) {
        int h = warp * 4 + hh;
        float sb = 0.f, sg = 0.f;
        for (int k2 = lane; k2 < HIDD; k2 += 32) {
            float xv = xs[k2];
            sb += xv * Wb[(size_t)h * HIDD + k2];
            sg += xv * Wgk[(size_t)h * HIDD + k2];
        }
#pragma unroll
        for (int off = 16; off; off >>= 1) {
            sb += __shfl_xor_sync(0xffffffffu, sb, off);
            sg += __shfl_xor_sync(0xffffffffu, sg, off);
        }
        if (lane == 0) {
            beta[t * NH + h] = 1.f / (1.f + expf(-(sb + bb[h])));
            float z = sg + bgk[h] + dt_bias[h];
            float sp = fmaxf(z, 0.f) + log1pf(expf(-fabsf(z)));
            alpha[t * NH + h] = expf(-expf(A_log[h]) * sp);
        }
    }
}

// ---------------------------------------------------------------------------
// YaRN RoPE + l2norm, in-place. One warp per (t, h); blockIdx.y selects q/k.
// ---------------------------------------------------------------------------
__global__ __launch_bounds__(128) void rope_l2norm(float* __restrict__ q,
                                                   float* __restrict__ k) {
    int gw = blockIdx.x * 4 + (threadIdx.x >> 5);   // over T*H
    int lane = threadIdx.x & 31;
    int t = gw >> 5;
    int h = gw & 31;
    float* base = (blockIdx.y == 0 ? q : k) + (size_t)t * KD + h * DH;

    int m = (2 * lane) & 31;       // frequency index actually used (even ones only)
    double invf = pow(10000.0, -((double)(2 * m) / 64.0));
    double wl = 6.283185307179586 / invf;
    double ramp = (wl - 1.0) / 31.0;
    ramp = ramp < 0.0 ? 0.0 : (ramp > 1.0 ? 1.0 : ramp);
    double scale = 1.0 + 31.0 * ramp;
    float f = (float)(((double)t / scale) * invf);
    float s, c;
    sincosf(f, &s, &c);

    float x1 = base[2 * lane];
    float x2 = base[2 * lane + 1];
    __syncwarp();
    float lo = x1 * c - x2 * s;
    float hi = x1 * s + x2 * c;
    float ss = lo * lo + hi * hi;
#pragma unroll
    for (int off = 16; off; off >>= 1) ss += __shfl_xor_sync(0xffffffffu, ss, off);
    float r = rsqrtf(ss + 1e-6f);
    base[lane] = lo * r;
    base[lane + 32] = hi * r;
}

// ---------------------------------------------------------------------------
// Sequential delta-rule scan. One block per head; 128 threads.
// Thread owns column j = tid>>1, rows [half*32, half*32+32) of S (32 regs).
// Per step (folded alpha): errdot = k·S_old; err = v - a*errdot; u = beta*err;
// S = a*S + k*u; o = q·S.
// ---------------------------------------------------------------------------
#define CH 32
__global__ __launch_bounds__(128) void scan_kernel(const float* __restrict__ q,
                                                   const float* __restrict__ k,
                                                   const float* __restrict__ v,
                                                   const float* __restrict__ alpha,
                                                   const float* __restrict__ beta,
                                                   float* __restrict__ o) {
    int h = blockIdx.x;
    __shared__ __align__(16) float sq[CH][DH];
    __shared__ __align__(16) float sk[CH][DH];
    __shared__ __align__(16) float sv[CH][DH];
    __shared__ __align__(16) float so[CH][DH];
    __shared__ float sa[CH], sb2[CH];

    int tid = threadIdx.x;
    int j = tid >> 1;
    int half = tid & 1;
    int base = half * 32;

    float S[32];
#pragma unroll
    for (int i = 0; i < 32; i++) S[i] = 0.f;

    for (int t0 = 0; t0 < TT; t0 += CH) {
        // cooperative load of CH steps of q,k,v (each CH*64 floats = 512 float4)
#pragma unroll
        for (int r = 0; r < 4; r++) {
            int fi = tid + r * 128;      // 0..511
            int s = fi >> 4;             // step
            int d4 = fi & 15;            // float4 within 64
            size_t gidx = (size_t)(t0 + s) * KD + h * DH + d4 * 4;
            ((float4*)sq[s])[d4] = *(const float4*)&q[gidx];
            ((float4*)sk[s])[d4] = *(const float4*)&k[gidx];
            ((float4*)sv[s])[d4] = *(const float4*)&v[gidx];
        }
        if (tid < CH) {
            sa[tid]  = alpha[(t0 + tid) * NH + h];
            sb2[tid] = beta[(t0 + tid) * NH + h];
        }
        __syncthreads();

        for (int s = 0; s < CH; s++) {
            const float* kk = &sk[s][base];
            float e0 = 0.f, e1 = 0.f, e2 = 0.f, e3 = 0.f;
#pragma unroll
            for (int ii = 0; ii < 32; ii += 4) {
                float4 k4 = *(const float4*)&kk[ii];
                e0 += k4.x * S[ii];     e1 += k4.y * S[ii + 1];
                e2 += k4.z * S[ii + 2]; e3 += k4.w * S[ii + 3];
            }
            float errdot = (e0 + e1) + (e2 + e3);
            errdot += __shfl_xor_sync(0xffffffffu, errdot, 1);
            float a = sa[s];
            float u = sb2[s] * (sv[s][j] - a * errdot);
            const float* qq = &sq[s][base];
            float o0 = 0.f, o1 = 0.f, o2 = 0.f, o3 = 0.f;
#pragma unroll
            for (int ii = 0; ii < 32; ii += 4) {
                float4 k4 = *(const float4*)&kk[ii];
                float4 q4 = *(const float4*)&qq[ii];
                S[ii]     = fmaf(k4.x, u, a * S[ii]);
                S[ii + 1] = fmaf(k4.y, u, a * S[ii + 1]);
                S[ii + 2] = fmaf(k4.z, u, a * S[ii + 2]);
                S[ii + 3] = fmaf(k4.w, u, a * S[ii + 3]);
                o0 += q4.x * S[ii];     o1 += q4.y * S[ii + 1];
                o2 += q4.z * S[ii + 2]; o3 += q4.w * S[ii + 3];
            }
            float ov = (o0 + o1) + (o2 + o3);
            ov += __shfl_xor_sync(0xffffffffu, ov, 1);
            if (half == 0) so[s][j] = ov;
        }
        __syncthreads();
        // store o chunk
#pragma unroll
        for (int r = 0; r < 4; r++) {
            int fi = tid + r * 128;
            int s = fi >> 4;
            int d4 = fi & 15;
            *(float4*)&o[(size_t)(t0 + s) * KD + h * DH + d4 * 4] = ((float4*)so[s])[d4];
        }
        // next-iteration load+sync protects so/sq/sk/sv reuse
    }
}

// ---------------------------------------------------------------------------
// Epilogue: o = o_scan + D[h]*v; RMS-norm over DH; out = gate * silu(onw * xn)
// One warp per (t, h); lane handles dims (lane, lane+32).
// ---------------------------------------------------------------------------
__global__ __launch_bounds__(128) void epilogue(const float* __restrict__ o_scan,
                                                const float* __restrict__ v,
                                                const float* __restrict__ gate,
                                                const float* __restrict__ D,
                                                const float* __restrict__ onw,
                                                float* __restrict__ out) {
    int gw = blockIdx.x * 4 + (threadIdx.x >> 5);
    int lane = threadIdx.x & 31;
    int t = gw >> 5, h = gw & 31;
    size_t base = (size_t)t * KD + h * DH;
    float d = D[h];
    float o0 = o_scan[base + lane]      + d * v[base + lane];
    float o1 = o_scan[base + lane + 32] + d * v[base + lane + 32];
    float ss = o0 * o0 + o1 * o1;
#pragma unroll
    for (int off = 16; off; off >>= 1) ss += __shfl_xor_sync(0xffffffffu, ss, off);
    float r = rsqrtf(ss * (1.f / 64.f) + 1e-6f);
    float z0 = onw[lane]      * o0 * r;
    float z1 = onw[lane + 32] * o1 * r;
    out[base + lane]      = gate[base + lane]      * z0 / (1.f + expf(-z0));
    out[base + lane + 32] = gate[base + lane + 32] * z1 / (1.f + expf(-z1));
}

// ---------------------------------------------------------------------------
extern "C" void kernel_launch(void* const* d_in, const int* in_sizes, int n_in,
                              void* d_out, int out_size) {
    const float* x       = (const float*)d_in[0];
    const float* Wq      = (const float*)d_in[1];
    const float* Wk      = (const float*)d_in[2];
    const float* Wv      = (const float*)d_in[3];
    const float* Wg      = (const float*)d_in[4];
    const float* Wo      = (const float*)d_in[5];
    const float* Wb      = (const float*)d_in[6];
    const float* bb      = (const float*)d_in[7];
    const float* Wgk     = (const float*)d_in[8];
    const float* bgk     = (const float*)d_in[9];
    const float* wq_conv = (const float*)d_in[10];
    const float* bq_conv = (const float*)d_in[11];
    const float* wk_conv = (const float*)d_in[12];
    const float* bk_conv = (const float*)d_in[13];
    const float* wv_conv = (const float*)d_in[14];
    const float* bv_conv = (const float*)d_in[15];
    const float* A_log   = (const float*)d_in[16];
    const float* Dp      = (const float*)d_in[17];
    const float* dt_bias = (const float*)d_in[18];
    const float* onorm_w = (const float*)d_in[19];
    float* out = (float*)d_out;

    float* S;
    cudaGetSymbolAddress((void**)&S, g_scratch);
    float* bq  = S + OFF_Q;
    float* bk  = S + OFF_K;
    float* bv  = S + OFF_V;
    float* bg  = S + OFF_G;
    float* bqc = S + OFF_QC;
    float* bkc = S + OFF_KC;
    float* bvc = S + OFF_VC;
    float* bo  = S + OFF_O;
    float* bal = S + OFF_AL;
    float* bbe = S + OFF_BE;

    dim3 g16(16, 16);
    sgemm_nt<<<g16, 256>>>(x, Wq, bq, TT, KD, HIDD);
    sgemm_nt<<<g16, 256>>>(x, Wk, bk, TT, KD, HIDD);
    sgemm_nt<<<g16, 256>>>(x, Wv, bv, TT, KD, HIDD);
    sgemm_nt<<<g16, 256>>>(x, Wg, bg, TT, KD, HIDD);

    small_proj<<<TT, 256>>>(x, Wb, bb, Wgk, bgk, A_log, dt_bias, bal, bbe);

    conv_silu<<<TT * KD / 256, 256>>>(bq, wq_conv, bq_conv, bqc);
    conv_silu<<<TT * KD / 256, 256>>>(bk, wk_conv, bk_conv, bkc);
    conv_silu<<<TT * KD / 256, 256>>>(bv, wv_conv, bv_conv, bvc);

    dim3 gr(TT * NH / 4, 2);
    rope_l2norm<<<gr, 128>>>(bqc, bkc);

    scan_kernel<<<NH, 128>>>(bqc, bkc, bvc, bal, bbe, bo);

    epilogue<<<TT * NH / 4, 128>>>(bo, bvc, bg, Dp, onorm_w, bq /* reuse as o2 */);

    sgemm_nt<<<g16, 256>>>(bq, Wo, out, TT, HIDD, KD);
}

// round 2
// speedup vs baseline: 2.3337x; 2.3337x over previous
#include <cuda_runtime.h>
#include <math.h>
#include <stdint.h>

#define TT 2048
#define HIDD 2048
#define NH 32
#define DH 64
#define KD 2048
#define NE (2048u*2048u)

// Scratch: q,k,v,g projections; qc,kc,vc post-conv; o scan output; alpha/beta.
__device__ __align__(16) float g_scratch[8ull*NE + 2ull*TT*NH];

#define OFF_Q  (0ull*NE)
#define OFF_K  (1ull*NE)
#define OFF_V  (2ull*NE)
#define OFF_G  (3ull*NE)
#define OFF_QC (4ull*NE)
#define OFF_KC (5ull*NE)
#define OFF_VC (6ull*NE)
#define OFF_O  (7ull*NE)
#define OFF_AL (8ull*NE)
#define OFF_BE (8ull*NE + (unsigned long long)TT*NH)

// ---------------------------------------------------------------------------
// TF32 tensor-core NT GEMM: C[m,n] = sum_k A[m*K+k] * B[n*K+k]
// 128x128 block tile, BK=32, 4 warps (2x2) of 64x64, mma.sync.m16n8k8.tf32.
// cp.async double-buffered smem; stride-36 padding -> conflict-free LDS.
// ---------------------------------------------------------------------------
#define SPAD 36
#define ASZ (128*SPAD)
#define GEMM_SMEM (2u*2u*ASZ*4u)   // 73728 bytes

__device__ __forceinline__ uint32_t f2tf(float f) {
    uint32_t u;
    asm("cvt.rna.tf32.f32 %0, %1;" : "=r"(u) : "f"(f));
    return u;
}

__device__ __forceinline__ void mma8(float* c, const uint32_t* a, const uint32_t* b) {
    asm volatile(
        "mma.sync.aligned.m16n8k8.row.col.f32.tf32.tf32.f32 "
        "{%0,%1,%2,%3},{%4,%5,%6,%7},{%8,%9},{%0,%1,%2,%3};\n"
        : "+f"(c[0]), "+f"(c[1]), "+f"(c[2]), "+f"(c[3])
        : "r"(a[0]), "r"(a[1]), "r"(a[2]), "r"(a[3]), "r"(b[0]), "r"(b[1]));
}

__device__ __forceinline__ void cp_async16(uint32_t saddr, const void* gptr) {
    asm volatile("cp.async.ca.shared.global [%0], [%1], 16;\n" :: "r"(saddr), "l"(gptr));
}

__global__ __launch_bounds__(128) void gemm_tf32(const float* __restrict__ A,
                                                 const float* __restrict__ B,
                                                 float* __restrict__ C,
                                                 int M, int N, int K) {
    extern __shared__ float sm[];
    const int tid = threadIdx.x;
    const int warp = tid >> 5, lane = tid & 31;
    const int grp = lane >> 2, tig = lane & 3;
    const int wm = (warp >> 1) * 64, wn = (warp & 1) * 64;
    const int bx = blockIdx.x, by = blockIdx.y;

    const float* Ag = A + (size_t)(by * 128) * K;
    const float* Bg = B + (size_t)(bx * 128) * K;

    float c[4][8][4];
#pragma unroll
    for (int mi = 0; mi < 4; mi++)
#pragma unroll
        for (int nj = 0; nj < 8; nj++)
#pragma unroll
            for (int r = 0; r < 4; r++) c[mi][nj][r] = 0.f;

    const uint32_t smbase = (uint32_t)__cvta_generic_to_shared(sm);
    const int NK = K / 32;

    // issue cp.async for stage s, k-tile kt
    auto issue = [&](int s, int kt) {
        uint32_t As = smbase + (uint32_t)(s * 2 * ASZ) * 4u;
        uint32_t Bs = As + ASZ * 4u;
#pragma unroll
        for (int i = 0; i < 8; i++) {
            int idx = i * 128 + tid;
            int r = idx >> 3;
            int k4 = (idx & 7) * 4;
            cp_async16(As + (uint32_t)(r * SPAD + k4) * 4u,
                       Ag + (size_t)r * K + kt * 32 + k4);
            cp_async16(Bs + (uint32_t)(r * SPAD + k4) * 4u,
                       Bg + (size_t)r * K + kt * 32 + k4);
        }
        asm volatile("cp.async.commit_group;\n");
    };

    issue(0, 0);

    for (int kt = 0; kt < NK; kt++) {
        const int s = kt & 1;
        if (kt + 1 < NK) {
            issue((kt + 1) & 1, kt + 1);
            asm volatile("cp.async.wait_group 1;\n");
        } else {
            asm volatile("cp.async.wait_group 0;\n");
        }
        __syncthreads();

        const float* As = sm + s * 2 * ASZ;
        const float* Bs = As + ASZ;

#pragma unroll
        for (int ks = 0; ks < 4; ks++) {
            const int k = ks * 8;
            uint32_t av[4][4], bv[8][2];
#pragma unroll
            for (int mi = 0; mi < 4; mi++) {
                const int m = wm + mi * 16 + grp;
                av[mi][0] = f2tf(As[m * SPAD + k + tig]);
                av[mi][1] = f2tf(As[(m + 8) * SPAD + k + tig]);
                av[mi][2] = f2tf(As[m * SPAD + k + tig + 4]);
                av[mi][3] = f2tf(As[(m + 8) * SPAD + k + tig + 4]);
            }
#pragma unroll
            for (int nj = 0; nj < 8; nj++) {
                const int n = wn + nj * 8 + grp;
                bv[nj][0] = f2tf(Bs[n * SPAD + k + tig]);
                bv[nj][1] = f2tf(Bs[n * SPAD + k + tig + 4]);
            }
#pragma unroll
            for (int mi = 0; mi < 4; mi++)
#pragma unroll
                for (int nj = 0; nj < 8; nj++)
                    mma8(c[mi][nj], av[mi], bv[nj]);
        }
        __syncthreads();
    }

    // epilogue
#pragma unroll
    for (int mi = 0; mi < 4; mi++) {
        const int gm = by * 128 + wm + mi * 16 + grp;
#pragma unroll
        for (int nj = 0; nj < 8; nj++) {
            const int gn = bx * 128 + wn + nj * 8 + 2 * tig;
            *(float2*)(C + (size_t)gm * N + gn) = make_float2(c[mi][nj][0], c[mi][nj][1]);
            *(float2*)(C + (size_t)(gm + 8) * N + gn) = make_float2(c[mi][nj][2], c[mi][nj][3]);
        }
    }
}

// ---------------------------------------------------------------------------
// Causal depthwise conv (K=4) + SiLU.  One thread per (t, c).
// ---------------------------------------------------------------------------
__global__ __launch_bounds__(256) void conv_silu(const float* __restrict__ in,
                                                 const float* __restrict__ w,
                                                 const float* __restrict__ b,
                                                 float* __restrict__ out) {
    unsigned idx = blockIdx.x * 256u + threadIdx.x;   // t*KD + c
    int c = idx & (KD - 1);
    int t = idx >> 11;
    float4 w4 = ((const float4*)w)[c];
    float y = b[c];
    int ts = t - 3;
    if (ts >= 0)     y += in[(size_t)ts * KD + c] * w4.x;
    if (ts + 1 >= 0) y += in[(size_t)(ts + 1) * KD + c] * w4.y;
    if (ts + 2 >= 0) y += in[(size_t)(ts + 2) * KD + c] * w4.z;
    y += in[(size_t)t * KD + c] * w4.w;
    out[idx] = y / (1.f + expf(-y));   // silu
}

// ---------------------------------------------------------------------------
// beta / alpha projections.
// ---------------------------------------------------------------------------
__global__ __launch_bounds__(256) void small_proj(const float* __restrict__ x,
                                                  const float* __restrict__ Wb,
                                                  const float* __restrict__ bb,
                                                  const float* __restrict__ Wgk,
                                                  const float* __restrict__ bgk,
                                                  const float* __restrict__ A_log,
                                                  const float* __restrict__ dt_bias,
                                                  float* __restrict__ alpha,
                                                  float* __restrict__ beta) {
    __shared__ __align__(16) float xs[HIDD];
    int t = blockIdx.x;
    for (int i = threadIdx.x; i < HIDD / 4; i += 256)
        ((float4*)xs)[i] = ((const float4*)(x + (size_t)t * HIDD))[i];
    __syncthreads();
    int warp = threadIdx.x >> 5, lane = threadIdx.x & 31;
#pragma unroll
    for (int hh = 0; hh < 4; hh++) {
        int h = warp * 4 + hh;
        float sb = 0.f, sg = 0.f;
        for (int k2 = lane; k2 < HIDD; k2 += 32) {
            float xv = xs[k2];
            sb += xv * Wb[(size_t)h * HIDD + k2];
            sg += xv * Wgk[(size_t)h * HIDD + k2];
        }
#pragma unroll
        for (int off = 16; off; off >>= 1) {
            sb += __shfl_xor_sync(0xffffffffu, sb, off);
            sg += __shfl_xor_sync(0xffffffffu, sg, off);
        }
        if (lane == 0) {
            beta[t * NH + h] = 1.f / (1.f + expf(-(sb + bb[h])));
            float z = sg + bgk[h] + dt_bias[h];
            float sp = fmaxf(z, 0.f) + log1pf(expf(-fabsf(z)));
            alpha[t * NH + h] = expf(-expf(A_log[h]) * sp);
        }
    }
}

// ---------------------------------------------------------------------------
// YaRN RoPE + l2norm, in-place. One warp per (t, h); blockIdx.y selects q/k.
// ---------------------------------------------------------------------------
__global__ __launch_bounds__(128) void rope_l2norm(float* __restrict__ q,
                                                   float* __restrict__ k) {
    int gw = blockIdx.x * 4 + (threadIdx.x >> 5);   // over T*H
    int lane = threadIdx.x & 31;
    int t = gw >> 5;
    int h = gw & 31;
    float* base = (blockIdx.y == 0 ? q : k) + (size_t)t * KD + h * DH;

    int m = (2 * lane) & 31;
    double invf = pow(10000.0, -((double)(2 * m) / 64.0));
    double wl = 6.283185307179586 / invf;
    double ramp = (wl - 1.0) / 31.0;
    ramp = ramp < 0.0 ? 0.0 : (ramp > 1.0 ? 1.0 : ramp);
    double scale = 1.0 + 31.0 * ramp;
    float f = (float)(((double)t / scale) * invf);
    float s, c;
    sincosf(f, &s, &c);

    float x1 = base[2 * lane];
    float x2 = base[2 * lane + 1];
    __syncwarp();
    float lo = x1 * c - x2 * s;
    float hi = x1 * s + x2 * c;
    float ss = lo * lo + hi * hi;
#pragma unroll
    for (int off = 16; off; off >>= 1) ss += __shfl_xor_sync(0xffffffffu, ss, off);
    float r = rsqrtf(ss + 1e-6f);
    base[lane] = lo * r;
    base[lane + 32] = hi * r;
}

// ---------------------------------------------------------------------------
// Sequential delta-rule scan. One block per head; 128 threads.
// ---------------------------------------------------------------------------
#define CH 32
__global__ __launch_bounds__(128) void scan_kernel(const float* __restrict__ q,
                                                   const float* __restrict__ k,
                                                   const float* __restrict__ v,
                                                   const float* __restrict__ alpha,
                                                   const float* __restrict__ beta,
                                                   float* __restrict__ o) {
    int h = blockIdx.x;
    __shared__ __align__(16) float sq[CH][DH];
    __shared__ __align__(16) float sk[CH][DH];
    __shared__ __align__(16) float sv[CH][DH];
    __shared__ __align__(16) float so[CH][DH];
    __shared__ float sa[CH], sb2[CH];

    int tid = threadIdx.x;
    int j = tid >> 1;
    int half = tid & 1;
    int base = half * 32;

    float S[32];
#pragma unroll
    for (int i = 0; i < 32; i++) S[i] = 0.f;

    for (int t0 = 0; t0 < TT; t0 += CH) {
#pragma unroll
        for (int r = 0; r < 4; r++) {
            int fi = tid + r * 128;
            int s = fi >> 4;
            int d4 = fi & 15;
            size_t gidx = (size_t)(t0 + s) * KD + h * DH + d4 * 4;
            ((float4*)sq[s])[d4] = *(const float4*)&q[gidx];
            ((float4*)sk[s])[d4] = *(const float4*)&k[gidx];
            ((float4*)sv[s])[d4] = *(const float4*)&v[gidx];
        }
        if (tid < CH) {
            sa[tid]  = alpha[(t0 + tid) * NH + h];
            sb2[tid] = beta[(t0 + tid) * NH + h];
        }
        __syncthreads();

        for (int s = 0; s < CH; s++) {
            const float* kk = &sk[s][base];
            float e0 = 0.f, e1 = 0.f, e2 = 0.f, e3 = 0.f;
#pragma unroll
            for (int ii = 0; ii < 32; ii += 4) {
                float4 k4 = *(const float4*)&kk[ii];
                e0 += k4.x * S[ii];     e1 += k4.y * S[ii + 1];
                e2 += k4.z * S[ii + 2]; e3 += k4.w * S[ii + 3];
            }
            float errdot = (e0 + e1) + (e2 + e3);
            errdot += __shfl_xor_sync(0xffffffffu, errdot, 1);
            float a = sa[s];
            float u = sb2[s] * (sv[s][j] - a * errdot);
            const float* qq = &sq[s][base];
            float o0 = 0.f, o1 = 0.f, o2 = 0.f, o3 = 0.f;
#pragma unroll
            for (int ii = 0; ii < 32; ii += 4) {
                float4 k4 = *(const float4*)&kk[ii];
                float4 q4 = *(const float4*)&qq[ii];
                S[ii]     = fmaf(k4.x, u, a * S[ii]);
                S[ii + 1] = fmaf(k4.y, u, a * S[ii + 1]);
                S[ii + 2] = fmaf(k4.z, u, a * S[ii + 2]);
                S[ii + 3] = fmaf(k4.w, u, a * S[ii + 3]);
                o0 += q4.x * S[ii];     o1 += q4.y * S[ii + 1];
                o2 += q4.z * S[ii + 2]; o3 += q4.w * S[ii + 3];
            }
            float ov = (o0 + o1) + (o2 + o3);
            ov += __shfl_xor_sync(0xffffffffu, ov, 1);
            if (half == 0) so[s][j] = ov;
        }
        __syncthreads();
#pragma unroll
        for (int r = 0; r < 4; r++) {
            int fi = tid + r * 128;
            int s = fi >> 4;
            int d4 = fi & 15;
            *(float4*)&o[(size_t)(t0 + s) * KD + h * DH + d4 * 4] = ((float4*)so[s])[d4];
        }
    }
}

// ---------------------------------------------------------------------------
// Epilogue: o = o_scan + D[h]*v; RMS-norm over DH; out = gate * silu(onw * xn)
// ---------------------------------------------------------------------------
__global__ __launch_bounds__(128) void epilogue(const float* __restrict__ o_scan,
                                                const float* __restrict__ v,
                                                const float* __restrict__ gate,
                                                const float* __restrict__ D,
                                                const float* __restrict__ onw,
                                                float* __restrict__ out) {
    int gw = blockIdx.x * 4 + (threadIdx.x >> 5);
    int lane = threadIdx.x & 31;
    int t = gw >> 5, h = gw & 31;
    size_t base = (size_t)t * KD + h * DH;
    float d = D[h];
    float o0 = o_scan[base + lane]      + d * v[base + lane];
    float o1 = o_scan[base + lane + 32] + d * v[base + lane + 32];
    float ss = o0 * o0 + o1 * o1;
#pragma unroll
    for (int off = 16; off; off >>= 1) ss += __shfl_xor_sync(0xffffffffu, ss, off);
    float r = rsqrtf(ss * (1.f / 64.f) + 1e-6f);
    float z0 = onw[lane]      * o0 * r;
    float z1 = onw[lane + 32] * o1 * r;
    out[base + lane]      = gate[base + lane]      * z0 / (1.f + expf(-z0));
    out[base + lane + 32] = gate[base + lane + 32] * z1 / (1.f + expf(-z1));
}

// ---------------------------------------------------------------------------
extern "C" void kernel_launch(void* const* d_in, const int* in_sizes, int n_in,
                              void* d_out, int out_size) {
    const float* x       = (const float*)d_in[0];
    const float* Wq      = (const float*)d_in[1];
    const float* Wk      = (const float*)d_in[2];
    const float* Wv      = (const float*)d_in[3];
    const float* Wg      = (const float*)d_in[4];
    const float* Wo      = (const float*)d_in[5];
    const float* Wb      = (const float*)d_in[6];
    const float* bb      = (const float*)d_in[7];
    const float* Wgk     = (const float*)d_in[8];
    const float* bgk     = (const float*)d_in[9];
    const float* wq_conv = (const float*)d_in[10];
    const float* bq_conv = (const float*)d_in[11];
    const float* wk_conv = (const float*)d_in[12];
    const float* bk_conv = (const float*)d_in[13];
    const float* wv_conv = (const float*)d_in[14];
    const float* bv_conv = (const float*)d_in[15];
    const float* A_log   = (const float*)d_in[16];
    const float* Dp      = (const float*)d_in[17];
    const float* dt_bias = (const float*)d_in[18];
    const float* onorm_w = (const float*)d_in[19];
    float* out = (float*)d_out;

    float* S;
    cudaGetSymbolAddress((void**)&S, g_scratch);
    float* bq  = S + OFF_Q;
    float* bk  = S + OFF_K;
    float* bv  = S + OFF_V;
    float* bg  = S + OFF_G;
    float* bqc = S + OFF_QC;
    float* bkc = S + OFF_KC;
    float* bvc = S + OFF_VC;
    float* bo  = S + OFF_O;
    float* bal = S + OFF_AL;
    float* bbe = S + OFF_BE;

    static int smem_set = 0;
    if (!smem_set) {
        cudaFuncSetAttribute(gemm_tf32, cudaFuncAttributeMaxDynamicSharedMemorySize,
                             GEMM_SMEM);
        smem_set = 1;
    }

    dim3 g16(16, 16);
    gemm_tf32<<<g16, 128, GEMM_SMEM>>>(x, Wq, bq, TT, KD, HIDD);
    gemm_tf32<<<g16, 128, GEMM_SMEM>>>(x, Wk, bk, TT, KD, HIDD);
    gemm_tf32<<<g16, 128, GEMM_SMEM>>>(x, Wv, bv, TT, KD, HIDD);
    gemm_tf32<<<g16, 128, GEMM_SMEM>>>(x, Wg, bg, TT, KD, HIDD);

    small_proj<<<TT, 256>>>(x, Wb, bb, Wgk, bgk, A_log, dt_bias, bal, bbe);

    conv_silu<<<TT * KD / 256, 256>>>(bq, wq_conv, bq_conv, bqc);
    conv_silu<<<TT * KD / 256, 256>>>(bk, wk_conv, bk_conv, bkc);
    conv_silu<<<TT * KD / 256, 256>>>(bv, wv_conv, bv_conv, bvc);

    dim3 gr(TT * NH / 4, 2);
    rope_l2norm<<<gr, 128>>>(bqc, bkc);

    scan_kernel<<<NH, 128>>>(bqc, bkc, bvc, bal, bbe, bo);

    epilogue<<<TT * NH / 4, 128>>>(bo, bvc, bg, Dp, onorm_w, bq /* reuse as o2 */);

    gemm_tf32<<<g16, 128, GEMM_SMEM>>>(bq, Wo, out, TT, HIDD, KD);
}